// round 17
// baseline (speedup 1.0000x reference)
#include <cuda_runtime.h>
#include <cuda_fp16.h>
#include <math.h>
#include <stdint.h>

#define SEQ    2048
#define HDIM   1024
#define NH     16
#define HS     64
#define MTOT   4096            // B*S
#define N_QKV  3072            // 3*HDIM

// Scratch (allocation-free rule: device globals)
__device__ __half   g_xh   [(size_t)MTOT * HDIM];        // half(x)
__device__ __half   g_xph  [(size_t)MTOT * HDIM];        // half(x+pos)
__device__ __half   g_aoh  [(size_t)MTOT * HDIM];        // attention out, half
__device__ __half   g_qkh  [(size_t)MTOT * 2048];        // q|k half (q pre-scaled)
__device__ __half   g_vT   [(size_t)HDIM * MTOT];        // v transposed
__device__ uint32_t g_wqkvT2[(size_t)N_QKV * (HDIM / 2)]; // W_qkv^T half2 (q scaled)
__device__ uint32_t g_woutT2[(size_t)HDIM * (HDIM / 2)];  // W_out^T half2

// ---------------------------------------------------------------------------
// helpers
// ---------------------------------------------------------------------------
__device__ __forceinline__ uint32_t f22h2(float x, float y) {
    __half2 h = __floats2half2_rn(x, y);
    return *(uint32_t*)&h;
}
__device__ __forceinline__ float ex2(float x) {
    float r;
    asm("ex2.approx.ftz.f32 %0, %1;" : "=f"(r) : "f"(x));
    return r;
}
__device__ __forceinline__ uint32_t ex2h2(float a, float b) {
    uint32_t arg = f22h2(a, b), r;
    asm("ex2.approx.f16x2 %0, %1;" : "=r"(r) : "r"(arg));
    return r;
}
__device__ __forceinline__ uint32_t smem_u32(const void* p) {
    uint32_t a;
    asm("{ .reg .u64 t; cvta.to.shared.u64 t, %1; cvt.u32.u64 %0, t; }"
        : "=r"(a) : "l"(p));
    return a;
}

#define MMA16(d, a, b)                                                         \
    asm volatile(                                                              \
        "mma.sync.aligned.m16n8k16.row.col.f32.f16.f16.f32 "                   \
        "{%0,%1,%2,%3},{%4,%5,%6,%7},{%8,%9},{%0,%1,%2,%3};"                   \
        : "+f"((d)[0]), "+f"((d)[1]), "+f"((d)[2]), "+f"((d)[3])               \
        : "r"((a)[0]), "r"((a)[1]), "r"((a)[2]), "r"((a)[3]),                  \
          "r"((b)[0]), "r"((b)[1]))

#define LDSM4(r0, r1, r2, r3, addr)                                            \
    asm volatile("ldmatrix.sync.aligned.m8n8.x4.shared.b16 {%0,%1,%2,%3}, [%4];" \
        : "=r"(r0), "=r"(r1), "=r"(r2), "=r"(r3) : "r"(addr))

#define CP16(dst_u32, src_ptr)                                                 \
    asm volatile("cp.async.cg.shared.global [%0], [%1], 16;"                   \
        :: "r"(dst_u32), "l"(src_ptr))
#define CP_COMMIT() asm volatile("cp.async.commit_group;" ::: "memory")
#define CP_WAIT(n)  asm volatile("cp.async.wait_group %0;" :: "n"(n) : "memory")

// ---------------------------------------------------------------------------
// merged prep (R16-exact): x conversion + weight transposes (Q cols x 1/8)
// ---------------------------------------------------------------------------
__global__ __launch_bounds__(256)
void prep_all(const float* __restrict__ x, const float* __restrict__ pos,
              const float* __restrict__ Wqkv, const float* __restrict__ Wout,
              __half* __restrict__ xh, __half* __restrict__ xph,
              uint32_t* __restrict__ wqkvT2, uint32_t* __restrict__ woutT2)
{
    const int bid = blockIdx.x;
    const int tid = threadIdx.x;

    if (bid < MTOT) {
        const int m = bid;
        const int c = tid * 4;
        float4 xv = *(const float4*)(x + (size_t)m * HDIM + c);
        float4 pv = *(const float4*)(pos + (size_t)(m & (SEQ - 1)) * HDIM + c);
        uint2 u0; u0.x = f22h2(xv.x, xv.y); u0.y = f22h2(xv.z, xv.w);
        *(uint2*)(xh + (size_t)m * HDIM + c) = u0;
        uint2 u1; u1.x = f22h2(xv.x + pv.x, xv.y + pv.y);
        u1.y = f22h2(xv.z + pv.z, xv.w + pv.w);
        *(uint2*)(xph + (size_t)m * HDIM + c) = u1;
        return;
    }

    __shared__ float tile[32][33];
    const float* W;
    uint32_t* WT2;
    int bx, by, N;
    bool isqkv;
    if (bid < MTOT + 3072) {
        int id = bid - MTOT;
        W = Wqkv; WT2 = wqkvT2; N = N_QKV; isqkv = true;
        bx = id % (N_QKV / 32);
        by = id / (N_QKV / 32);
    } else {
        int id = bid - MTOT - 3072;
        W = Wout; WT2 = woutT2; N = HDIM; isqkv = false;
        bx = id % (HDIM / 32);
        by = id / (HDIM / 32);
    }
    const int K = HDIM;
    const int tx = tid & 31;
    const int ty = tid >> 5;
    #pragma unroll
    for (int i = ty; i < 32; i += 8)
        tile[i][tx] = W[(size_t)(by * 32 + i) * N + bx * 32 + tx];
    __syncthreads();
    const float scl = (isqkv && bx * 32 < 1024) ? 0.125f : 1.0f;
    #pragma unroll
    for (int it = 0; it < 2; it++) {
        int id = tid + it * 256;
        int nl = id >> 4;
        int kh = id & 15;
        WT2[(size_t)(bx * 32 + nl) * (K / 2) + by * 16 + kh] =
            f22h2(tile[2 * kh][nl] * scl, tile[2 * kh + 1][nl] * scl);
    }
}

// ---------------------------------------------------------------------------
// fp16 GEMM: CTA tile 64(M) x 256(N), 512 thr, warp tile 16x64, K-step 64,
// 2-stage double buffer, ONE barrier per 64-k iteration, 2 CTAs/SM.
// Halved M-tile: halves wave-quantization tail loss (CTA duration halves),
// gives full-chip 1-wave for gemm2 (grid 256 over 296 slots).
// Rows at 36-word stride (ldmatrix conflict-free).
// ---------------------------------------------------------------------------
#define GEMM_A_WORDS (64 * 36)       // 2304
#define GEMM_B_WORDS (256 * 36)      // 9216
#define GEMM_STG     (GEMM_A_WORDS + GEMM_B_WORDS)
#define GEMM_SMEM    (2 * GEMM_STG * 4)   // 92160 B -> 2 CTAs/SM

__global__ __launch_bounds__(512, 2)
void gemm_h16(const __half* __restrict__ A0, const __half* __restrict__ A1,
              const uint32_t* __restrict__ BT2, float* __restrict__ Cf,
              __half* __restrict__ qkh, __half* __restrict__ vT,
              int N, int K, int ncut, int outmode)
{
    extern __shared__ uint32_t gsm[];
    const uint32_t s_u = smem_u32(gsm);

    const int tid  = threadIdx.x;
    const int lane = tid & 31;
    const int warp = tid >> 5;
    const int wm   = warp >> 2;         // 0..3 (16-row band)
    const int wn   = warp & 3;          // 0..3 (64-col band)
    const int g    = lane >> 2;
    const int t    = lane & 3;

    const int m0 = blockIdx.y * 64;
    const int n0 = blockIdx.x * 256;
    const __half* Aptr = (n0 < ncut) ? A0 : A1;

    const int lrow = lane & 15;
    const int lckA = lane >> 4;
    const int lnB  = (lane & 7) + 8 * ((lane >> 4) & 1);
    const int lckB = (lane >> 3) & 1;

    auto stage = [&](int tt, int bf) {
        const int k0 = tt << 6;
        const uint32_t abase = s_u + (uint32_t)(bf * GEMM_STG) * 4;
        const uint32_t bbase = abase + GEMM_A_WORDS * 4;
        {   // A: 64 rows x 8 chunks = 512 CP16 (1 per thread)
            int row = tid >> 3;
            int ch  = tid & 7;
            CP16(abase + (uint32_t)(row * 36 + ch * 4) * 4,
                 Aptr + (size_t)(m0 + row) * K + k0 + ch * 8);
        }
        #pragma unroll
        for (int it = 0; it < 4; it++) {
            int id = tid + it * 512;
            int n  = id >> 3;
            int ch = id & 7;
            CP16(bbase + (uint32_t)(n * 36 + ch * 4) * 4,
                 BT2 + (size_t)(n0 + n) * (K / 2) + (k0 >> 1) + ch * 4);
        }
    };

    float acc[8][4];
    #pragma unroll
    for (int j = 0; j < 8; j++)
        #pragma unroll
        for (int c = 0; c < 4; c++)
            acc[j][c] = 0.0f;

    const int T = K >> 6;
    stage(0, 0); CP_COMMIT();

    for (int tt = 0; tt < T; tt++) {
        const int bf = tt & 1;
        CP_WAIT(0);
        __syncthreads();
        if (tt + 1 < T) {
            stage(tt + 1, bf ^ 1);
            CP_COMMIT();
        }

        const uint32_t ab = s_u + (uint32_t)(bf * GEMM_STG) * 4;
        const uint32_t bb = ab + GEMM_A_WORDS * 4;
        #pragma unroll
        for (int ks = 0; ks < 4; ks++) {
            uint32_t afr[4], bfr[8][2];
            {
                int row = wm * 16 + lrow;
                LDSM4(afr[0], afr[1], afr[2], afr[3],
                      ab + (uint32_t)(row * 36 + (2 * ks + lckA) * 4) * 4);
            }
            #pragma unroll
            for (int p = 0; p < 4; p++) {
                int n = wn * 64 + p * 16 + lnB;
                LDSM4(bfr[2 * p][0], bfr[2 * p][1],
                      bfr[2 * p + 1][0], bfr[2 * p + 1][1],
                      bb + (uint32_t)(n * 36 + (2 * ks + lckB) * 4) * 4);
            }
            #pragma unroll
            for (int ni = 0; ni < 8; ni++)
                MMA16(acc[ni], afr, bfr[ni]);
        }
    }

    // ---- epilogue ----
    const int row = m0 + wm * 16 + g;
    if (outmode == 0) {
        #pragma unroll
        for (int ni = 0; ni < 8; ni++) {
            int col = n0 + wn * 64 + ni * 8 + 2 * t;
            *(float2*)(Cf + (size_t)row * N + col) =
                make_float2(acc[ni][0], acc[ni][1]);
            *(float2*)(Cf + (size_t)(row + 8) * N + col) =
                make_float2(acc[ni][2], acc[ni][3]);
        }
    } else if (n0 < 2048) {
        #pragma unroll
        for (int ni = 0; ni < 8; ni++) {
            int col = n0 + wn * 64 + ni * 8 + 2 * t;
            *(uint32_t*)(qkh + (size_t)row * 2048 + col) =
                f22h2(acc[ni][0], acc[ni][1]);
            *(uint32_t*)(qkh + (size_t)(row + 8) * 2048 + col) =
                f22h2(acc[ni][2], acc[ni][3]);
        }
    } else {
        #pragma unroll
        for (int ni = 0; ni < 8; ni++) {
            int colv = n0 - 2048 + wn * 64 + ni * 8 + 2 * t;
            vT[(size_t)colv * MTOT + row]           = __float2half_rn(acc[ni][0]);
            vT[(size_t)(colv + 1) * MTOT + row]     = __float2half_rn(acc[ni][1]);
            vT[(size_t)colv * MTOT + row + 8]       = __float2half_rn(acc[ni][2]);
            vT[(size_t)(colv + 1) * MTOT + row + 8] = __float2half_rn(acc[ni][3]);
        }
    }
}

// ---------------------------------------------------------------------------
// Flash attention (causal) — R16-exact: LPT grid (x=bh, y=qtile descending),
// Q pre-scaled via weights, f16x2 exp, MMA row-sums, early staging,
// double-buffered cp.async, Q/P in regs, 1 sync/tile, 2 CTAs/SM.
// ---------------------------------------------------------------------------
#define ATTN_SMEM_BYTES (4 * 4096 * 4)

__global__ __launch_bounds__(256, 2)
void attn_h16(const __half* __restrict__ qkh, const __half* __restrict__ vT,
              __half* __restrict__ aoh)
{
    extern __shared__ uint32_t usm[];
    const uint32_t usm_u = smem_u32(usm);

    const int tid  = threadIdx.x;
    const int lane = tid & 31;
    const int warp = tid >> 5;
    const int g    = lane >> 2;
    const int t    = lane & 3;
    const int q0   = warp * 16;
    const unsigned FULL = 0xffffffffu;

    const int lnB  = (lane & 7) + 8 * ((lane >> 4) & 1);
    const int lckB = (lane >> 3) & 1;

    const int bh = blockIdx.x;
    const int b  = bh >> 4;
    const int h  = bh & 15;
    const int qt = (int)gridDim.y - 1 - (int)blockIdx.y;

    uint32_t qf[4][4];
    {
        const __half* qb = qkh + (size_t)(b * SEQ + qt * 128 + q0 + g) * 2048 + h * HS;
        #pragma unroll
        for (int ks = 0; ks < 4; ks++) {
            qf[ks][0] = *(const uint32_t*)(qb + ks * 16 + 2 * t);
            qf[ks][1] = *(const uint32_t*)(qb + 8 * 2048 + ks * 16 + 2 * t);
            qf[ks][2] = *(const uint32_t*)(qb + ks * 16 + 2 * t + 8);
            qf[ks][3] = *(const uint32_t*)(qb + 8 * 2048 + ks * 16 + 2 * t + 8);
        }
    }

    const __half* kb0 = qkh + (size_t)(b * SEQ) * 2048 + 1024 + h * HS;
    const __half* vb0 = vT + (size_t)(h * HS) * MTOT + b * SEQ;

    auto stageKV = [&](int kt2, int bf) {
        const uint32_t kbase = usm_u + (uint32_t)(bf * 8192) * 4;
        const __half* kb = kb0 + (size_t)(kt2 * 128) * 2048;
        #pragma unroll
        for (int it = 0; it < 4; it++) {
            int id  = tid + it * 256;
            int key = id >> 3;
            int ch  = id & 7;
            CP16(kbase + (uint32_t)(((key << 5) + ((ch ^ (key & 7)) << 2)) << 2),
                 kb + (size_t)key * 2048 + ch * 8);
        }
        const __half* vb = vb0 + kt2 * 128;
        #pragma unroll
        for (int it = 0; it < 4; it++) {
            int id = tid + it * 256;
            int d  = id >> 4;
            int ch = id & 15;
            CP16(kbase + 4096 * 4 +
                     (uint32_t)((d * 64 + ((ch ^ (d & 7)) << 2)) << 2),
                 vb + (size_t)d * MTOT + ch * 8);
        }
    };

    float m0r = -1e30f, m1r = -1e30f, l0r = 0.0f, l1r = 0.0f;
    float o[8][4];
    #pragma unroll
    for (int ni = 0; ni < 8; ni++)
        o[ni][0] = o[ni][1] = o[ni][2] = o[ni][3] = 0.0f;

    const float L2E = 1.4426950408889634f;
    const uint32_t ONES2 = 0x3C003C00u;

    stageKV(0, 0); CP_COMMIT();
    CP_WAIT(0);
    __syncthreads();

    int buf = 0;
    for (int kt = 0; kt <= qt; kt++) {
        const uint32_t kb_u = usm_u + (uint32_t)(buf * 8192) * 4;
        const uint32_t vb_u = kb_u + 4096 * 4;

        // ---- S = Q @ K^T ----
        float sacc[16][4];
        #pragma unroll
        for (int ni = 0; ni < 16; ni++)
            sacc[ni][0] = sacc[ni][1] = sacc[ni][2] = sacc[ni][3] = 0.0f;

        #pragma unroll
        for (int ks = 0; ks < 4; ks++) {
            #pragma unroll
            for (int p = 0; p < 8; p++) {
                int key = p * 16 + lnB;
                int ck  = 2 * ks + lckB;
                uint32_t addr = kb_u +
                    (uint32_t)(((key << 5) + ((ck ^ (key & 7)) << 2)) << 2);
                uint32_t b0, b1, b2, b3;
                LDSM4(b0, b1, b2, b3, addr);
                uint32_t f0[2] = { b0, b1 };
                uint32_t f1[2] = { b2, b3 };
                MMA16(sacc[2 * p],     qf[ks], f0);
                MMA16(sacc[2 * p + 1], qf[ks], f1);
            }
        }

        // ---- causal mask (diagonal tile only) ----
        const int r0l = q0 + g, r1l = r0l + 8;
        if (kt == qt) {
            #pragma unroll
            for (int ni = 0; ni < 16; ni++) {
                int c = ni * 8 + 2 * t;
                if (c     > r0l) sacc[ni][0] = -1e30f;
                if (c + 1 > r0l) sacc[ni][1] = -1e30f;
                if (c     > r1l) sacc[ni][2] = -1e30f;
                if (c + 1 > r1l) sacc[ni][3] = -1e30f;
            }
        }

        // ---- stage next K/V tile EARLY ----
        if (kt < qt) {
            stageKV(kt + 1, buf ^ 1);
            CP_COMMIT();
        }

        // ---- row max (quad reduce) ----
        float rm0 = -1e30f, rm1 = -1e30f;
        #pragma unroll
        for (int ni = 0; ni < 16; ni++) {
            rm0 = fmaxf(rm0, fmaxf(sacc[ni][0], sacc[ni][1]));
            rm1 = fmaxf(rm1, fmaxf(sacc[ni][2], sacc[ni][3]));
        }
        rm0 = fmaxf(rm0, __shfl_xor_sync(FULL, rm0, 1));
        rm0 = fmaxf(rm0, __shfl_xor_sync(FULL, rm0, 2));
        rm1 = fmaxf(rm1, __shfl_xor_sync(FULL, rm1, 1));
        rm1 = fmaxf(rm1, __shfl_xor_sync(FULL, rm1, 2));

        float nm0 = fmaxf(m0r, rm0), nm1 = fmaxf(m1r, rm1);
        float fac0 = ex2((m0r - nm0) * L2E), fac1 = ex2((m1r - nm1) * L2E);
        float nb0 = nm0 * L2E, nb1 = nm1 * L2E;

        // ---- exp via f16x2 MUFU: result is the packed P fragment ----
        uint32_t p01[16], p23[16];
        #pragma unroll
        for (int ni = 0; ni < 16; ni++) {
            p01[ni] = ex2h2(fmaf(sacc[ni][0], L2E, -nb0),
                            fmaf(sacc[ni][1], L2E, -nb0));
            p23[ni] = ex2h2(fmaf(sacc[ni][2], L2E, -nb1),
                            fmaf(sacc[ni][3], L2E, -nb1));
        }

        m0r = nm0; m1r = nm1;
        #pragma unroll
        for (int ni = 0; ni < 8; ni++) {
            o[ni][0] *= fac0; o[ni][1] *= fac0;
            o[ni][2] *= fac1; o[ni][3] *= fac1;
        }

        // ---- O += P @ V, row-sums via ones-column MMA ----
        float rsum[4] = {0.0f, 0.0f, 0.0f, 0.0f};
        #pragma unroll
        for (int kk = 0; kk < 8; kk++) {
            uint32_t afr[4] = { p01[2 * kk], p23[2 * kk],
                                p01[2 * kk + 1], p23[2 * kk + 1] };
            #pragma unroll
            for (int p = 0; p < 4; p++) {
                int d  = p * 16 + lnB;
                int ck = 2 * kk + lckB;
                uint32_t addr = vb_u +
                    (uint32_t)(((d << 6) + ((ck ^ (d & 7)) << 2)) << 2);
                uint32_t b0, b1, b2, b3;
                LDSM4(b0, b1, b2, b3, addr);
                uint32_t f0[2] = { b0, b1 };
                uint32_t f1[2] = { b2, b3 };
                MMA16(o[2 * p],     afr, f0);
                MMA16(o[2 * p + 1], afr, f1);
            }
            uint32_t of[2] = { ONES2, ONES2 };
            MMA16(rsum, afr, of);
        }

        l0r = l0r * fac0 + rsum[0];
        l1r = l1r * fac1 + rsum[2];

        if (kt < qt) {
            CP_WAIT(0);
            __syncthreads();
            buf ^= 1;
        }
    }

    // ---- normalize + write half ao ----
    float inv0 = 1.0f / l0r, inv1 = 1.0f / l1r;
    __half* aobase = aoh + (size_t)(b * SEQ + qt * 128) * HDIM + h * HS;
    #pragma unroll
    for (int ni = 0; ni < 8; ni++) {
        int c = ni * 8 + 2 * t;
        *(uint32_t*)(aobase + (size_t)(q0 + g) * HDIM + c) =
            f22h2(o[ni][0] * inv0, o[ni][1] * inv0);
        *(uint32_t*)(aobase + (size_t)(q0 + g + 8) * HDIM + c) =
            f22h2(o[ni][2] * inv1, o[ni][3] * inv1);
    }
}

// ---------------------------------------------------------------------------
extern "C" void kernel_launch(void* const* d_in, const int* in_sizes, int n_in,
                              void* d_out, int out_size)
{
    const float* x    = (const float*)d_in[0];
    const float* pos  = (const float*)d_in[1];
    const float* Wqkv = (const float*)d_in[2];
    const float* Wout = (const float*)d_in[3];
    float* out = (float*)d_out;

    __half *xh_p, *xph_p, *aoh_p, *qkh_p, *vT_p;
    uint32_t *wqkvT2_p, *woutT2_p;
    cudaGetSymbolAddress((void**)&xh_p,     g_xh);
    cudaGetSymbolAddress((void**)&xph_p,    g_xph);
    cudaGetSymbolAddress((void**)&aoh_p,    g_aoh);
    cudaGetSymbolAddress((void**)&qkh_p,    g_qkh);
    cudaGetSymbolAddress((void**)&vT_p,     g_vT);
    cudaGetSymbolAddress((void**)&wqkvT2_p, g_wqkvT2);
    cudaGetSymbolAddress((void**)&woutT2_p, g_woutT2);

    // 0) merged prep (Q-scale folded into Wqkv transpose)
    prep_all<<<MTOT + 3072 + 1024, 256>>>(x, pos, Wqkv, Wout,
                                          xh_p, xph_p, wqkvT2_p, woutT2_p);

    // 1) qkv projection (64x256 tiles, 2 CTAs/SM, halved tail loss)
    {
        cudaFuncSetAttribute(gemm_h16,
                             cudaFuncAttributeMaxDynamicSharedMemorySize, GEMM_SMEM);
        dim3 grid(N_QKV / 256, MTOT / 64);
        gemm_h16<<<grid, 512, GEMM_SMEM>>>(xph_p, xh_p, wqkvT2_p, nullptr,
                                           qkh_p, vT_p, N_QKV, HDIM, 2048, 1);
    }

    // 2) flash attention (R16-exact, LPT dispatch)
    {
        cudaFuncSetAttribute(attn_h16,
                             cudaFuncAttributeMaxDynamicSharedMemorySize, ATTN_SMEM_BYTES);
        dim3 grid(2 * NH, SEQ / 128);
        attn_h16<<<grid, 256, ATTN_SMEM_BYTES>>>(qkh_p, vT_p, aoh_p);
    }

    // 3) out = ao @ Wout (64x256 tiles, grid 256 -> full chip, 1 wave)
    {
        dim3 grid(HDIM / 256, MTOT / 64);
        gemm_h16<<<grid, 512, GEMM_SMEM>>>(aoh_p, aoh_p, woutT2_p, out,
                                           nullptr, nullptr, HDIM, HDIM, 0, 0);
    }
}